// round 2
// baseline (speedup 1.0000x reference)
#include <cuda_runtime.h>

// Problem constants
#define B_SZ   4096
#define E_SZ   128
#define IP_SZ  64
#define H_SZ   100
#define HP     128      // padded H (weight tiles zero-padded to 128 cols)
#define ROWS   128      // rows (batch elements) per CTA
#define THREADS 512     // 16 warps, 8 rows each (4 f32x2 row-pairs)
#define XS     65       // padded x-plane stride (conflict-free transpose writes)

#define USE_F32X2 1     // flip to 0 if ptxas rejects fma.rn.f32x2 on sm_103a

// ---------- f32x2 packed helpers ----------
__device__ __forceinline__ unsigned long long pk2(float a, float b) {
    unsigned long long d;
    asm("mov.b64 %0, {%1, %2};" : "=l"(d) : "f"(a), "f"(b));
    return d;
}
__device__ __forceinline__ float2 upk2(unsigned long long v) {
    float2 r;
    asm("mov.b64 {%0, %1}, %2;" : "=f"(r.x), "=f"(r.y) : "l"(v));
    return r;
}
__device__ __forceinline__ unsigned long long ffma2(unsigned long long a,
                                                    unsigned long long b,
                                                    unsigned long long c) {
#if USE_F32X2
    unsigned long long d;
    asm("fma.rn.f32x2 %0, %1, %2, %3;" : "=l"(d) : "l"(a), "l"(b), "l"(c));
    return d;
#else
    float2 af = upk2(a), bf = upk2(b), cf = upk2(c);
    return pk2(fmaf(af.x, bf.x, cf.x), fmaf(af.y, bf.y, cf.y));
#endif
}

// Per-pair epilogue: +bias, LeakyReLU(0.01), LayerNorm over the 100 real cols.
__device__ __forceinline__ void bias_leaky_ln_pair(
    const unsigned long long accp[4], const int j[4], const bool jv[4],
    const float* __restrict__ bias, const float* __restrict__ gam,
    const float* __restrict__ bet, float2 hv[4])
{
    float2 s = make_float2(0.f, 0.f);
    float2 q = make_float2(0.f, 0.f);
#pragma unroll
    for (int c = 0; c < 4; c++) {
        float2 a = upk2(accp[c]);
        if (jv[c]) {
            float bb = bias[j[c]];
            a.x += bb; a.y += bb;
            a.x = a.x > 0.f ? a.x : 0.01f * a.x;
            a.y = a.y > 0.f ? a.y : 0.01f * a.y;
            s.x += a.x; s.y += a.y;
            q.x += a.x * a.x; q.y += a.y * a.y;
        } else {
            a.x = 0.f; a.y = 0.f;
        }
        hv[c] = a;
    }
#pragma unroll
    for (int m = 16; m; m >>= 1) {
        s.x += __shfl_xor_sync(0xffffffffu, s.x, m);
        s.y += __shfl_xor_sync(0xffffffffu, s.y, m);
        q.x += __shfl_xor_sync(0xffffffffu, q.x, m);
        q.y += __shfl_xor_sync(0xffffffffu, q.y, m);
    }
    const float inv = 1.0f / (float)H_SZ;
    float mx = s.x * inv, my = s.y * inv;
    float vx = q.x * inv - mx * mx;
    float vy = q.y * inv - my * my;
    float rx = rsqrtf(vx + 1e-5f);
    float ry = rsqrtf(vy + 1e-5f);
#pragma unroll
    for (int c = 0; c < 4; c++) {
        if (jv[c]) {
            float g = gam[j[c]], bt = bet[j[c]];
            hv[c].x = (hv[c].x - mx) * rx * g + bt;
            hv[c].y = (hv[c].y - my) * ry * g + bt;
        }
    }
}

// Shared memory layout (floats):
//   W1P : 64*128  = 8192
//   W2P : 100*128 = 12800
//   vec : b1|g1|be1|b2|g2|be2|Wo (7*100) + bo = 704
//   xA/xB : 64*65 each (even/odd row planes, [i][rp])
//   hA/hB : 64*100 each ([rp][j])
#define SMEM_FLOATS (8192 + 12800 + 704 + 4160 + 4160 + 6400 + 6400)

__global__ __launch_bounds__(THREADS, 1)
void fused_edge_mlp_kernel(
    const float* __restrict__ gx,  const float* __restrict__ gW1,
    const float* __restrict__ gb1, const float* __restrict__ gg1,
    const float* __restrict__ gbe1,const float* __restrict__ gW2,
    const float* __restrict__ gb2, const float* __restrict__ gg2,
    const float* __restrict__ gbe2,const float* __restrict__ gWo,
    const float* __restrict__ gbo, float* __restrict__ out)
{
    extern __shared__ float sm[];
    float* W1P = sm;                       // [64][128]
    float* W2P = W1P + 64 * HP;            // [100][128]
    float* vec = W2P + H_SZ * HP;          // 704
    float* xA  = vec + 704;                // [64][65]
    float* xB  = xA + 64 * XS;
    float* hA  = xB + 64 * XS;             // [64][100]
    float* hB  = hA + 64 * H_SZ;

    const int e   = blockIdx.x;
    const int b0  = blockIdx.y * ROWS;
    const int tid = threadIdx.x;

    // ---- stage weights ----
    {
        // W1: 64x100 -> 64x128 zero-padded. Vector path: each row is 100
        // floats = 25 float4's. 64 rows * 25 = 1600 float4 loads.
        const float4* w1v = (const float4*)(gW1 + (size_t)e * IP_SZ * H_SZ);
        for (int idx = tid; idx < IP_SZ * 25; idx += THREADS) {
            int i = idx / 25, c4 = idx % 25;
            float4 v = w1v[idx];             // row-major contiguous: i*25+c4
            float* dst = &W1P[i * HP + c4 * 4];
            dst[0] = v.x; dst[1] = v.y; dst[2] = v.z; dst[3] = v.w;
        }
        // zero pad cols [100,128)
        for (int idx = tid; idx < IP_SZ * 28; idx += THREADS) {
            int i = idx / 28, jj = 100 + idx % 28;
            W1P[i * HP + jj] = 0.f;
        }
        const float4* w2v = (const float4*)(gW2 + (size_t)e * H_SZ * H_SZ);
        for (int idx = tid; idx < H_SZ * 25; idx += THREADS) {
            int i = idx / 25, c4 = idx % 25;
            float4 v = w2v[idx];
            float* dst = &W2P[i * HP + c4 * 4];
            dst[0] = v.x; dst[1] = v.y; dst[2] = v.z; dst[3] = v.w;
        }
        for (int idx = tid; idx < H_SZ * 28; idx += THREADS) {
            int i = idx / 28, jj = 100 + idx % 28;
            W2P[i * HP + jj] = 0.f;
        }
        if (tid < H_SZ) {
            vec[           tid] = gb1 [e * H_SZ + tid];
            vec[1 * H_SZ + tid] = gg1 [e * H_SZ + tid];
            vec[2 * H_SZ + tid] = gbe1[e * H_SZ + tid];
            vec[3 * H_SZ + tid] = gb2 [e * H_SZ + tid];
            vec[4 * H_SZ + tid] = gg2 [e * H_SZ + tid];
            vec[5 * H_SZ + tid] = gbe2[e * H_SZ + tid];
            vec[6 * H_SZ + tid] = gWo [e * H_SZ + tid];
        }
        if (tid == 0) vec[700] = gbo[e];

        // ---- stage x chunk into even/odd row planes, [i][row_pair] ----
        for (int idx = tid; idx < ROWS * IP_SZ; idx += THREADS) {
            int r = idx >> 6, i = idx & 63;
            float v = gx[((size_t)(b0 + r) * E_SZ + e) * IP_SZ + i];
            int rp = r >> 1;
            float* dst = (r & 1) ? xB : xA;
            dst[i * XS + rp] = v;
        }
    }
    __syncthreads();

    const int warp  = tid >> 5;
    const int lane  = tid & 31;
    const int pbase = warp * 4;     // first row-pair of this warp

    int  j[4];
    bool jv[4];
#pragma unroll
    for (int c = 0; c < 4; c++) { j[c] = lane + 32 * c; jv[c] = (j[c] < H_SZ); }

    unsigned long long acc[4][4];
#pragma unroll
    for (int p = 0; p < 4; p++)
#pragma unroll
        for (int c = 0; c < 4; c++) acc[p][c] = 0ull;

    // ---- layer 1 mainloop: 8 rows x 128 cols over K=64 ----
#pragma unroll 4
    for (int i = 0; i < IP_SZ; i++) {
        unsigned long long xv[4];
#pragma unroll
        for (int p = 0; p < 4; p++)
            xv[p] = pk2(xA[i * XS + pbase + p], xB[i * XS + pbase + p]);
#pragma unroll
        for (int c = 0; c < 4; c++) {
            float wv = W1P[i * HP + j[c]];
            unsigned long long wd = pk2(wv, wv);
#pragma unroll
            for (int p = 0; p < 4; p++) acc[p][c] = ffma2(xv[p], wd, acc[p][c]);
        }
    }

    // ---- layer-1 epilogue: bias + leaky + LN -> smem h planes ----
#pragma unroll
    for (int p = 0; p < 4; p++) {
        float2 hv[4];
        bias_leaky_ln_pair(acc[p], j, jv, vec, vec + 100, vec + 200, hv);
#pragma unroll
        for (int c = 0; c < 4; c++) {
            if (jv[c]) {
                hA[(pbase + p) * H_SZ + j[c]] = hv[c].x;
                hB[(pbase + p) * H_SZ + j[c]] = hv[c].y;
            }
        }
#pragma unroll
        for (int c = 0; c < 4; c++) acc[p][c] = 0ull;
    }
    __syncwarp();   // h planes are private to this warp's 4 row-pairs

    // ---- layer 2 mainloop: 8 rows x 128 cols over K=100 ----
#pragma unroll 2
    for (int k = 0; k < H_SZ; k++) {
        unsigned long long xv[4];
#pragma unroll
        for (int p = 0; p < 4; p++)
            xv[p] = pk2(hA[(pbase + p) * H_SZ + k], hB[(pbase + p) * H_SZ + k]);
#pragma unroll
        for (int c = 0; c < 4; c++) {
            float wv = W2P[k * HP + j[c]];
            unsigned long long wd = pk2(wv, wv);
#pragma unroll
            for (int p = 0; p < 4; p++) acc[p][c] = ffma2(xv[p], wd, acc[p][c]);
        }
    }

    // ---- layer-2 epilogue + head ----
#pragma unroll
    for (int p = 0; p < 4; p++) {
        float2 hv[4];
        bias_leaky_ln_pair(acc[p], j, jv, vec + 300, vec + 400, vec + 500, hv);

        float2 d = make_float2(0.f, 0.f);
#pragma unroll
        for (int c = 0; c < 4; c++) {
            if (jv[c]) {
                float wv = vec[600 + j[c]];
                d.x += hv[c].x * wv;
                d.y += hv[c].y * wv;
            }
        }
#pragma unroll
        for (int m = 16; m; m >>= 1) {
            d.x += __shfl_xor_sync(0xffffffffu, d.x, m);
            d.y += __shfl_xor_sync(0xffffffffu, d.y, m);
        }
        if (lane == 0) {
            float bov = vec[700];
            int r = (pbase + p) * 2;                   // local even row
            size_t base = (size_t)e * B_SZ + b0 + r;   // out[e*B + b]
            out[base]     = d.x + bov;
            out[base + 1] = d.y + bov;
        }
    }
}

extern "C" void kernel_launch(void* const* d_in, const int* in_sizes, int n_in,
                              void* d_out, int out_size)
{
    const float* x   = (const float*)d_in[0];
    const float* W1  = (const float*)d_in[1];
    const float* b1  = (const float*)d_in[2];
    const float* g1  = (const float*)d_in[3];
    const float* be1 = (const float*)d_in[4];
    const float* W2  = (const float*)d_in[5];
    const float* b2  = (const float*)d_in[6];
    const float* g2  = (const float*)d_in[7];
    const float* be2 = (const float*)d_in[8];
    const float* Wo  = (const float*)d_in[9];
    const float* bo  = (const float*)d_in[10];
    float* out = (float*)d_out;

    const size_t smem = (size_t)SMEM_FLOATS * sizeof(float);   // 171264 B
    cudaFuncSetAttribute(fused_edge_mlp_kernel,
                         cudaFuncAttributeMaxDynamicSharedMemorySize, (int)smem);

    dim3 grid(E_SZ, B_SZ / ROWS);   // (128, 32)
    fused_edge_mlp_kernel<<<grid, THREADS, smem>>>(
        x, W1, b1, g1, be1, W2, b2, g2, be2, Wo, bo, out);
}

// round 9
// speedup vs baseline: 1.5485x; 1.5485x over previous
#include <cuda_runtime.h>

// Problem constants
#define B_SZ   4096
#define E_SZ   128
#define IP_SZ  64
#define H_SZ   100
#define HP     128      // padded H (weight tiles zero-padded to 128 cols)
#define ROWS   128      // rows (batch elements) per CTA
#define THREADS 512     // 16 warps, 8 rows each (4 f32x2 row-pairs)
#define XPS    65       // padded pair-stride of xP planes (bank-conflict fix)

// ---------- f32x2 packed helpers ----------
__device__ __forceinline__ unsigned long long pk2(float a, float b) {
    unsigned long long d;
    asm("mov.b64 %0, {%1, %2};" : "=l"(d) : "f"(a), "f"(b));
    return d;
}
__device__ __forceinline__ float2 upk2(unsigned long long v) {
    float2 r;
    asm("mov.b64 {%0, %1}, %2;" : "=f"(r.x), "=f"(r.y) : "l"(v));
    return r;
}
__device__ __forceinline__ unsigned long long ffma2(unsigned long long a,
                                                    unsigned long long b,
                                                    unsigned long long c) {
    unsigned long long d;
    asm("fma.rn.f32x2 %0, %1, %2, %3;" : "=l"(d) : "l"(a), "l"(b), "l"(c));
    return d;
}

// Per-pair epilogue: +bias, LeakyReLU(0.01), LayerNorm over the 100 real cols.
__device__ __forceinline__ void bias_leaky_ln_pair(
    const unsigned long long accp[4], const int j[4], const bool jv[4],
    const float* __restrict__ bias, const float* __restrict__ gam,
    const float* __restrict__ bet, float2 hv[4])
{
    float2 s = make_float2(0.f, 0.f);
    float2 q = make_float2(0.f, 0.f);
#pragma unroll
    for (int c = 0; c < 4; c++) {
        float2 a = upk2(accp[c]);
        if (jv[c]) {
            float bb = bias[j[c]];
            a.x += bb; a.y += bb;
            a.x = a.x > 0.f ? a.x : 0.01f * a.x;
            a.y = a.y > 0.f ? a.y : 0.01f * a.y;
            s.x += a.x; s.y += a.y;
            q.x += a.x * a.x; q.y += a.y * a.y;
        } else {
            a.x = 0.f; a.y = 0.f;
        }
        hv[c] = a;
    }
#pragma unroll
    for (int m = 16; m; m >>= 1) {
        s.x += __shfl_xor_sync(0xffffffffu, s.x, m);
        s.y += __shfl_xor_sync(0xffffffffu, s.y, m);
        q.x += __shfl_xor_sync(0xffffffffu, q.x, m);
        q.y += __shfl_xor_sync(0xffffffffu, q.y, m);
    }
    const float inv = 1.0f / (float)H_SZ;
    float mx = s.x * inv, my = s.y * inv;
    float vx = q.x * inv - mx * mx;
    float vy = q.y * inv - my * my;
    float rx = rsqrtf(vx + 1e-5f);
    float ry = rsqrtf(vy + 1e-5f);
#pragma unroll
    for (int c = 0; c < 4; c++) {
        if (jv[c]) {
            float g = gam[j[c]], bt = bet[j[c]];
            hv[c].x = (hv[c].x - mx) * rx * g + bt;
            hv[c].y = (hv[c].y - my) * ry * g + bt;
        }
    }
}

// Shared memory (floats):
//   W1P : 64*128    = 8192
//   W2P : 100*128   = 12800
//   vec : 704
//   xP  : 64*65*2   = 8320   (packed (even,odd) pair per (i, row-pair), padded)
//   hP  : 64*100*2  = 12800  (packed pair per (row-pair, j))
#define SMEM_FLOATS (8192 + 12800 + 704 + 8320 + 12800)

__global__ __launch_bounds__(THREADS, 1)
void fused_edge_mlp_kernel(
    const float* __restrict__ gx,  const float* __restrict__ gW1,
    const float* __restrict__ gb1, const float* __restrict__ gg1,
    const float* __restrict__ gbe1,const float* __restrict__ gW2,
    const float* __restrict__ gb2, const float* __restrict__ gg2,
    const float* __restrict__ gbe2,const float* __restrict__ gWo,
    const float* __restrict__ gbo, float* __restrict__ out)
{
    extern __shared__ float sm[];
    float* W1P = sm;                        // [64][128]
    float* W2P = W1P + 64 * HP;             // [100][128]
    float* vec = W2P + H_SZ * HP;           // 704
    float* xPf = vec + 704;                 // [64][65] pairs, as floats
    float* hPf = xPf + 64 * XPS * 2;        // [64][100] pairs, as floats
    unsigned long long* xP = (unsigned long long*)xPf;   // 8B-aligned
    unsigned long long* hP = (unsigned long long*)hPf;

    const int e   = blockIdx.x;
    const int b0  = blockIdx.y * ROWS;
    const int tid = threadIdx.x;

    // ---- stage weights (vectorized, zero-padded to 128 cols) ----
    {
        const float4* w1v = (const float4*)(gW1 + (size_t)e * IP_SZ * H_SZ);
        for (int idx = tid; idx < IP_SZ * 25; idx += THREADS) {
            int i = idx / 25, c4 = idx % 25;
            float4 v = w1v[idx];
            float* dst = &W1P[i * HP + c4 * 4];
            dst[0] = v.x; dst[1] = v.y; dst[2] = v.z; dst[3] = v.w;
        }
        for (int idx = tid; idx < IP_SZ * 28; idx += THREADS) {
            int i = idx / 28, jj = 100 + idx % 28;
            W1P[i * HP + jj] = 0.f;
        }
        const float4* w2v = (const float4*)(gW2 + (size_t)e * H_SZ * H_SZ);
        for (int idx = tid; idx < H_SZ * 25; idx += THREADS) {
            int i = idx / 25, c4 = idx % 25;
            float4 v = w2v[idx];
            float* dst = &W2P[i * HP + c4 * 4];
            dst[0] = v.x; dst[1] = v.y; dst[2] = v.z; dst[3] = v.w;
        }
        for (int idx = tid; idx < H_SZ * 28; idx += THREADS) {
            int i = idx / 28, jj = 100 + idx % 28;
            W2P[i * HP + jj] = 0.f;
        }
        if (tid < H_SZ) {
            vec[           tid] = gb1 [e * H_SZ + tid];
            vec[1 * H_SZ + tid] = gg1 [e * H_SZ + tid];
            vec[2 * H_SZ + tid] = gbe1[e * H_SZ + tid];
            vec[3 * H_SZ + tid] = gb2 [e * H_SZ + tid];
            vec[4 * H_SZ + tid] = gg2 [e * H_SZ + tid];
            vec[5 * H_SZ + tid] = gbe2[e * H_SZ + tid];
            vec[6 * H_SZ + tid] = gWo [e * H_SZ + tid];
        }
        if (tid == 0) vec[700] = gbo[e];

        // ---- stage x into packed (even,odd) row-pair planes: xP[i][rp] ----
        // Padded stride XPS=65 pairs: store bank = (i*130 + rp*2 + half) % 32
        // now varies with i, cutting the 16-way write conflict to ~4-way.
        const float4* gx4 = (const float4*)gx;
        for (int idx = tid; idx < ROWS * 16; idx += THREADS) {
            int r = idx >> 4, i4 = idx & 15;
            float4 v = gx4[(((size_t)(b0 + r) * E_SZ + e) * IP_SZ >> 2) + i4];
            int rp = r >> 1, half = r & 1;
            int i = i4 * 4;
            xPf[((i + 0) * XPS + rp) * 2 + half] = v.x;
            xPf[((i + 1) * XPS + rp) * 2 + half] = v.y;
            xPf[((i + 2) * XPS + rp) * 2 + half] = v.z;
            xPf[((i + 3) * XPS + rp) * 2 + half] = v.w;
        }
    }
    __syncthreads();

    const int warp  = tid >> 5;
    const int lane  = tid & 31;
    const int pbase = warp * 4;     // first row-pair of this warp

    int  j[4];
    bool jv[4];
#pragma unroll
    for (int c = 0; c < 4; c++) { j[c] = lane + 32 * c; jv[c] = (j[c] < H_SZ); }

    unsigned long long acc[4][4];
#pragma unroll
    for (int p = 0; p < 4; p++)
#pragma unroll
        for (int c = 0; c < 4; c++) acc[p][c] = 0ull;

    // Hoisted bases: mainloop addressing becomes [base + const] LDS forms.
    const unsigned long long* xrow = xP + pbase;          // + i*XPS
    const float*              w1l  = W1P + lane;          // + i*HP + 32c
    const unsigned long long* hrow = hP + (size_t)pbase * H_SZ;  // + p*H_SZ + k
    const float*              w2l  = W2P + lane;          // + k*HP + 32c

    // ---- layer 1 mainloop: 8 rows x 128 cols over K=64 ----
#pragma unroll 8
    for (int i = 0; i < IP_SZ; i++) {
        unsigned long long xv[4];
#pragma unroll
        for (int p = 0; p < 4; p++)
            xv[p] = xrow[i * XPS + p];               // broadcast LDS.64
#pragma unroll
        for (int c = 0; c < 4; c++) {
            float wv = w1l[i * HP + 32 * c];
            unsigned long long wd = pk2(wv, wv);
#pragma unroll
            for (int p = 0; p < 4; p++) acc[p][c] = ffma2(xv[p], wd, acc[p][c]);
        }
    }

    // ---- layer-1 epilogue: bias + leaky + LN -> packed hP ----
#pragma unroll
    for (int p = 0; p < 4; p++) {
        float2 hv[4];
        bias_leaky_ln_pair(acc[p], j, jv, vec, vec + 100, vec + 200, hv);
#pragma unroll
        for (int c = 0; c < 4; c++) {
            if (jv[c])
                hP[(pbase + p) * H_SZ + j[c]] = pk2(hv[c].x, hv[c].y);  // STS.64
        }
#pragma unroll
        for (int c = 0; c < 4; c++) acc[p][c] = 0ull;
    }
    __syncwarp();   // h row-pairs are private to this warp

    // ---- layer 2 mainloop: 8 rows x 128 cols over K=100 ----
#pragma unroll 4
    for (int k = 0; k < H_SZ; k++) {
        unsigned long long xv[4];
#pragma unroll
        for (int p = 0; p < 4; p++)
            xv[p] = hrow[p * H_SZ + k];              // broadcast LDS.64
#pragma unroll
        for (int c = 0; c < 4; c++) {
            float wv = w2l[k * HP + 32 * c];
            unsigned long long wd = pk2(wv, wv);
#pragma unroll
            for (int p = 0; p < 4; p++) acc[p][c] = ffma2(xv[p], wd, acc[p][c]);
        }
    }

    // ---- layer-2 epilogue + head ----
#pragma unroll
    for (int p = 0; p < 4; p++) {
        float2 hv[4];
        bias_leaky_ln_pair(acc[p], j, jv, vec + 300, vec + 400, vec + 500, hv);

        float2 d = make_float2(0.f, 0.f);
#pragma unroll
        for (int c = 0; c < 4; c++) {
            if (jv[c]) {
                float wv = vec[600 + j[c]];
                d.x += hv[c].x * wv;
                d.y += hv[c].y * wv;
            }
        }
#pragma unroll
        for (int m = 16; m; m >>= 1) {
            d.x += __shfl_xor_sync(0xffffffffu, d.x, m);
            d.y += __shfl_xor_sync(0xffffffffu, d.y, m);
        }
        if (lane == 0) {
            float bov = vec[700];
            int r = (pbase + p) * 2;                   // local even row
            size_t base = (size_t)e * B_SZ + b0 + r;   // out[e*B + b]
            out[base]     = d.x + bov;
            out[base + 1] = d.y + bov;
        }
    }
}

extern "C" void kernel_launch(void* const* d_in, const int* in_sizes, int n_in,
                              void* d_out, int out_size)
{
    const float* x   = (const float*)d_in[0];
    const float* W1  = (const float*)d_in[1];
    const float* b1  = (const float*)d_in[2];
    const float* g1  = (const float*)d_in[3];
    const float* be1 = (const float*)d_in[4];
    const float* W2  = (const float*)d_in[5];
    const float* b2  = (const float*)d_in[6];
    const float* g2  = (const float*)d_in[7];
    const float* be2 = (const float*)d_in[8];
    const float* Wo  = (const float*)d_in[9];
    const float* bo  = (const float*)d_in[10];
    float* out = (float*)d_out;

    const size_t smem = (size_t)SMEM_FLOATS * sizeof(float);   // 171264 B
    cudaFuncSetAttribute(fused_edge_mlp_kernel,
                         cudaFuncAttributeMaxDynamicSharedMemorySize, (int)smem);

    dim3 grid(E_SZ, B_SZ / ROWS);   // (128, 32)
    fused_edge_mlp_kernel<<<grid, THREADS, smem>>>(
        x, W1, b1, g1, be1, W2, b2, g2, be2, Wo, bo, out);
}